// round 9
// baseline (speedup 1.0000x reference)
#include <cuda_runtime.h>
#include <cuda_bf16.h>
#include <math.h>
#include <stdint.h>

// Problem constants
#define N_ 30000
#define D_ 128
#define E_ 240000
#define E2_ (E_ + N_)          // 270000
#define L_ 6
#define NEG_SLOPE 0.2f
#define EPS_ 1e-5f

// -------------------- device scratch --------------------
__device__ float g_h[N_ * D_];
__device__ float g_xg[N_ * D_];
__device__ float g_xl[N_ * D_];
__device__ float g_xr[N_ * D_];
// int8 limb-packed weights: [mat][w 0..31][n 0..127], word = 4 s8 along k
__device__ uint32_t g_B0[13 * 4096];
__device__ uint32_t g_B1[13 * 4096];
__device__ float    g_Binv[13 * 128];   // per-col inverse scale (max/126)

__device__ int    g_deg[N_];
__device__ int    g_cursor[N_];
__device__ int    g_rowptr[N_ + 1];
__device__ int    g_srcs[E2_];
__device__ int    g_scanbuf[30720];
__device__ int    g_bsum[32];

__device__ double g_lnred[12];
__device__ float  g_bnsum[D_];
__device__ float  g_bnsq[D_];

// -------------------- helpers --------------------
__device__ __forceinline__ void mma_s8(int* d, const uint32_t* a, const uint32_t* b) {
    asm volatile(
        "mma.sync.aligned.m16n8k32.row.col.s32.s8.s8.s32 "
        "{%0,%1,%2,%3}, {%4,%5,%6,%7}, {%8,%9}, {%0,%1,%2,%3};"
        : "+r"(d[0]), "+r"(d[1]), "+r"(d[2]), "+r"(d[3])
        : "r"(a[0]), "r"(a[1]), "r"(a[2]), "r"(a[3]), "r"(b[0]), "r"(b[1]));
}
__device__ __forceinline__ uint32_t pack4(int a, int b, int c, int d) {
    return (uint32_t)(a & 0xFF) | ((uint32_t)(b & 0xFF) << 8) |
           ((uint32_t)(c & 0xFF) << 16) | ((uint32_t)(d & 0xFF) << 24);
}
__device__ __forceinline__ void limbs(float x, float s, int& i0, int& i1) {
    float f = x * s;
    i0 = __float2int_rn(f);
    i1 = __float2int_rn((f - (float)i0) * 128.0f);
}
__device__ __forceinline__ float leaky(float v) { return v > 0.f ? v : NEG_SLOPE * v; }

// -------------------- small kernels --------------------
__global__ void zero_kernel() {
    int i = blockIdx.x * blockDim.x + threadIdx.x;
    if (i < N_) { g_deg[i] = 0; g_cursor[i] = 0; }
    if (i < 12) g_lnred[i] = 0.0;
    if (i < D_) { g_bnsum[i] = 0.f; g_bnsq[i] = 0.f; }
}

__global__ void gather_kernel(const int* __restrict__ x, const float* __restrict__ emb) {
    int i = blockIdx.x * blockDim.x + threadIdx.x;
    if (i >= N_ * 32) return;
    int n = i >> 5, c4 = i & 31;
    ((float4*)g_h)[i] = ((const float4*)(emb + (size_t)x[n] * D_))[c4];
}

__global__ void hist_kernel(const int* __restrict__ ei) {
    int e = blockIdx.x * blockDim.x + threadIdx.x;
    if (e >= E2_) return;
    int d = (e < E_) ? ei[E_ + e] : (e - E_);
    atomicAdd(&g_deg[d], 1);
}

__global__ void scan1_kernel() {
    __shared__ int sh[1024];
    int t = threadIdx.x, i = blockIdx.x * 1024 + t;
    int v = (i < N_) ? g_deg[i] : 0;
    sh[t] = v;
    __syncthreads();
    for (int o = 1; o < 1024; o <<= 1) {
        int u = (t >= o) ? sh[t - o] : 0;
        __syncthreads();
        sh[t] += u;
        __syncthreads();
    }
    g_scanbuf[i] = sh[t];
    if (t == 1023) g_bsum[blockIdx.x] = sh[1023];
}
__global__ void scan2_kernel() {
    int t = threadIdx.x;
    int orig = (t < 30) ? g_bsum[t] : 0;
    int v = orig;
    for (int o = 1; o < 32; o <<= 1) {
        int u = __shfl_up_sync(0xffffffffu, v, o);
        if (t >= o) v += u;
    }
    if (t < 30) g_bsum[t] = v - orig;
}
__global__ void scan3_kernel() {
    int t = threadIdx.x, i = blockIdx.x * 1024 + t;
    if (i > N_) return;
    int v = (i < N_) ? g_deg[i] : 0;
    g_rowptr[i] = g_bsum[blockIdx.x] + g_scanbuf[i] - v;
}

__global__ void scatter_kernel(const int* __restrict__ ei) {
    int e = blockIdx.x * blockDim.x + threadIdx.x;
    if (e >= E2_) return;
    int s, d;
    if (e < E_) { s = ei[e]; d = ei[E_ + e]; }
    else        { s = e - E_; d = s; }
    int pos = g_rowptr[d] + atomicAdd(&g_cursor[d], 1);
    g_srcs[pos] = s;
}

// per-column max of |W| -> inverse scale
__global__ void bcolmax_kernel(const float* __restrict__ Wl, const float* __restrict__ Wr,
                               const float* __restrict__ linW) {
    int mat = blockIdx.x, n = threadIdx.x;
    const float* src = (mat < 6) ? (Wl + mat * 16384)
                     : (mat < 12) ? (Wr + (mat - 6) * 16384) : linW;
    float m = 0.f;
    for (int k = 0; k < 128; k++) m = fmaxf(m, fabsf(src[k * D_ + n]));
    g_Binv[mat * 128 + n] = (m > 0.f) ? m / 126.0f : 0.f;
}

// pack W into int8 limbs [w][n]
__global__ void bpack_kernel(const float* __restrict__ Wl, const float* __restrict__ Wr,
                             const float* __restrict__ linW) {
    int idx = blockIdx.x * 256 + threadIdx.x;     // over 13*32*128
    if (idx >= 13 * 4096) return;
    int mat = idx / 4096;
    int rem = idx - mat * 4096;
    int w = rem >> 7;        // k-word 0..31 (4 k per word)
    int n = rem & 127;
    const float* src = (mat < 6) ? (Wl + mat * 16384)
                     : (mat < 12) ? (Wr + (mat - 6) * 16384) : linW;
    float inv = g_Binv[mat * 128 + n];
    float s = (inv > 0.f) ? 1.0f / inv : 0.f;
    int i0[4], i1[4];
#pragma unroll
    for (int j = 0; j < 4; j++)
        limbs(src[(4 * w + j) * D_ + n], s, i0[j], i1[j]);
    g_B0[mat * 4096 + w * 128 + n] = pack4(i0[0], i0[1], i0[2], i0[3]);
    g_B1[mat * 4096 + w * 128 + n] = pack4(i1[0], i1[1], i1[2], i1[3]);
}

// -------------------- int8 2-limb IMMA GEMM, M=64 tiles, B via L1 ----------
// PRE: 0 identity, 1 LN(graph)+ReLU, 2 A+resid.  NB: 1 or 2 weight matrices.
#define PW 36                        // words per row (32 + pad 4)
#define TILEU (64 * PW)              // 2304 words per limb array
#define GSMEM ((2 * TILEU + 64) * 4) // A0 + A1 + sInv[64] = 18688 B

template<int PRE, int NB>
__global__ __launch_bounds__(256, 2) void gat_gemm(
    const float* __restrict__ A, const float* __restrict__ resid,
    const uint32_t* __restrict__ B0A, const uint32_t* __restrict__ B1A,
    const uint32_t* __restrict__ B0B, const uint32_t* __restrict__ B1B,
    const float* __restrict__ tInvA, const float* __restrict__ tInvB,
    const float* __restrict__ biasA, const float* __restrict__ biasB,
    float* __restrict__ CA, float* __restrict__ CB,
    const float* __restrict__ lnG, const float* __restrict__ lnB, int lnslot)
{
    extern __shared__ uint32_t smu[];
    uint32_t* A0 = smu;
    uint32_t* A1 = smu + TILEU;
    float* sInv  = (float*)(smu + 2 * TILEU);

    const int tid = threadIdx.x, wid = tid >> 5, lane = tid & 31;
    const int row0 = blockIdx.x * 64;

    float mu = 0.f, inv = 0.f;
    if (PRE == 1) {
        double s  = g_lnred[lnslot * 2 + 0];
        double sq = g_lnred[lnslot * 2 + 1];
        const double cnt = (double)N_ * (double)D_;
        double m = s / cnt;
        mu  = (float)m;
        inv = (float)(1.0 / sqrt(sq / cnt - m * m + (double)EPS_));
    }

    // ---- stage A: pre-op, per-row scale, 2-limb int8 pack ----
    {
        const int r = tid >> 2, q = tid & 3;       // row, quarter (32 k each)
        const bool aok = (row0 + r) < N_;
        const float* Arow = A + (size_t)(row0 + r) * D_;
        const float* Rrow = (PRE == 2) ? (resid + (size_t)(row0 + r) * D_) : nullptr;
        float xs[32];
#pragma unroll
        for (int i = 0; i < 8; i++) {
            int c4 = q * 8 + i;                    // float4 idx 0..31
            float4 v = make_float4(0.f, 0.f, 0.f, 0.f);
            if (aok) v = *(const float4*)(Arow + c4 * 4);
            if (PRE == 1) {
                float4 lg = *(const float4*)(lnG + c4 * 4);
                float4 lb = *(const float4*)(lnB + c4 * 4);
                v.x = fmaxf((v.x - mu) * inv * lg.x + lb.x, 0.f);
                v.y = fmaxf((v.y - mu) * inv * lg.y + lb.y, 0.f);
                v.z = fmaxf((v.z - mu) * inv * lg.z + lb.z, 0.f);
                v.w = fmaxf((v.w - mu) * inv * lg.w + lb.w, 0.f);
            } else if (PRE == 2) {
                if (aok) {
                    float4 rv = *(const float4*)(Rrow + c4 * 4);
                    v.x += rv.x; v.y += rv.y; v.z += rv.z; v.w += rv.w;
                }
            }
            xs[i * 4 + 0] = v.x; xs[i * 4 + 1] = v.y;
            xs[i * 4 + 2] = v.z; xs[i * 4 + 3] = v.w;
        }
        float m = 0.f;
#pragma unroll
        for (int i = 0; i < 32; i++) m = fmaxf(m, fabsf(xs[i]));
        m = fmaxf(m, __shfl_xor_sync(0xffffffffu, m, 1));
        m = fmaxf(m, __shfl_xor_sync(0xffffffffu, m, 2));
        float s = (m > 0.f) ? 126.0f / m : 0.f;
        if (q == 0) sInv[r] = (m > 0.f) ? m / 126.0f : 0.f;
#pragma unroll
        for (int w = 0; w < 8; w++) {
            int i0[4], i1[4];
#pragma unroll
            for (int j = 0; j < 4; j++)
                limbs(xs[w * 4 + j], s, i0[j], i1[j]);
            A0[r * PW + q * 8 + w] = pack4(i0[0], i0[1], i0[2], i0[3]);
            A1[r * PW + q * 8 + w] = pack4(i1[0], i1[1], i1[2], i1[3]);
        }
    }
    __syncthreads();

    const int g  = lane >> 2;        // 0..7
    const int tg = lane & 3;         // 0..3
    const int wr = (wid >> 2) * 32;  // warp row slab (0/32)
    const int wc = (wid & 3) * 32;   // warp col slab

#pragma unroll
    for (int mat = 0; mat < NB; mat++) {
        const uint32_t* B0 = mat ? B0B : B0A;
        const uint32_t* B1 = mat ? B1B : B1A;
        const float* tInv  = mat ? tInvB : tInvA;
        const float* bias  = mat ? biasB : biasA;
        float* C           = mat ? CB : CA;

        int accm[2][4][4], accc[2][4][4];
#pragma unroll
        for (int mi = 0; mi < 2; mi++)
#pragma unroll
            for (int ni = 0; ni < 4; ni++)
#pragma unroll
                for (int j = 0; j < 4; j++) { accm[mi][ni][j] = 0; accc[mi][ni][j] = 0; }

#pragma unroll
        for (int ks = 0; ks < 4; ks++) {
            uint32_t a0[2][4], a1[2][4];
#pragma unroll
            for (int mi = 0; mi < 2; mi++) {
                int o1 = (wr + mi * 16 + g) * PW + ks * 8 + tg;
                int o2 = o1 + 8 * PW;
                a0[mi][0] = A0[o1]; a0[mi][1] = A0[o2];
                a0[mi][2] = A0[o1 + 4]; a0[mi][3] = A0[o2 + 4];
                a1[mi][0] = A1[o1]; a1[mi][1] = A1[o2];
                a1[mi][2] = A1[o1 + 4]; a1[mi][3] = A1[o2 + 4];
            }
            uint32_t b0[4][2], b1[4][2];
            const int bo = (ks * 8 + tg) * 128 + wc + g;
#pragma unroll
            for (int ni = 0; ni < 4; ni++) {
                b0[ni][0] = B0[bo + ni * 8];
                b0[ni][1] = B0[bo + 512 + ni * 8];
                b1[ni][0] = B1[bo + ni * 8];
                b1[ni][1] = B1[bo + 512 + ni * 8];
            }
#pragma unroll
            for (int mi = 0; mi < 2; mi++)
#pragma unroll
                for (int ni = 0; ni < 4; ni++)
                    mma_s8(accm[mi][ni], a0[mi], b0[ni]);
#pragma unroll
            for (int mi = 0; mi < 2; mi++)
#pragma unroll
                for (int ni = 0; ni < 4; ni++)
                    mma_s8(accc[mi][ni], a0[mi], b1[ni]);
#pragma unroll
            for (int mi = 0; mi < 2; mi++)
#pragma unroll
                for (int ni = 0; ni < 4; ni++)
                    mma_s8(accc[mi][ni], a1[mi], b0[ni]);
        }

        // ---- epilogue for this matrix ----
#pragma unroll
        for (int mi = 0; mi < 2; mi++) {
            int lr = wr + mi * 16 + g;
            int r1 = row0 + lr, r2 = r1 + 8;
            float si1 = sInv[lr], si2 = sInv[lr + 8];
#pragma unroll
            for (int ni = 0; ni < 4; ni++) {
                int col = wc + ni * 8 + tg * 2;
                float t0 = tInv[col], t1 = tInv[col + 1];
                float2 bv = *(const float2*)(bias + col);
                const int* pm = accm[mi][ni];
                const int* pc = accc[mi][ni];
                if (r1 < N_) {
                    float2 o;
                    o.x = ((float)pm[0] + (float)pc[0] * 0.0078125f) * si1 * t0 + bv.x;
                    o.y = ((float)pm[1] + (float)pc[1] * 0.0078125f) * si1 * t1 + bv.y;
                    *(float2*)(C + (size_t)r1 * D_ + col) = o;
                }
                if (r2 < N_) {
                    float2 o;
                    o.x = ((float)pm[2] + (float)pc[2] * 0.0078125f) * si2 * t0 + bv.x;
                    o.y = ((float)pm[3] + (float)pc[3] * 0.0078125f) * si2 * t1 + bv.y;
                    *(float2*)(C + (size_t)r2 * D_ + col) = o;
                }
            }
        }
    }
}

// -------------------- aggregation (warp per dst) + fused LN stats ----------
template<int STATS>
__global__ __launch_bounds__(256) void agg_kernel(
    const float* __restrict__ att, const float* __restrict__ cbias, int slot)
{
    __shared__ float ssum[8], ssq[8];
    int tid = threadIdx.x;
    int warp = (blockIdx.x * blockDim.x + tid) >> 5;
    int lane = tid & 31;
    int wid = tid >> 5;

    float4 o = make_float4(0.f, 0.f, 0.f, 0.f);
    if (warp < N_) {
        const float4 attv = ((const float4*)att)[lane];
        const float4 xrv  = ((const float4*)(g_xr + (size_t)warp * D_))[lane];
        int beg = g_rowptr[warp], end = g_rowptr[warp + 1];

        float m = -INFINITY, lsum = 0.f;
        float4 acc = make_float4(0.f, 0.f, 0.f, 0.f);
        for (int e = beg; e < end; e++) {
            int s = g_srcs[e];
            float4 v = ((const float4*)(g_xl + (size_t)s * D_))[lane];
            float p = leaky(v.x + xrv.x) * attv.x
                    + leaky(v.y + xrv.y) * attv.y
                    + leaky(v.z + xrv.z) * attv.z
                    + leaky(v.w + xrv.w) * attv.w;
#pragma unroll
            for (int of = 16; of > 0; of >>= 1)
                p += __shfl_xor_sync(0xffffffffu, p, of);
            float mn    = fmaxf(m, p);
            float scale = __expf(m - mn);
            float w     = __expf(p - mn);
            acc.x = acc.x * scale + w * v.x;
            acc.y = acc.y * scale + w * v.y;
            acc.z = acc.z * scale + w * v.z;
            acc.w = acc.w * scale + w * v.w;
            lsum  = lsum * scale + w;
            m = mn;
        }
        float invl = 1.f / lsum;
        float4 cb = ((const float4*)cbias)[lane];
        o = make_float4(acc.x * invl + cb.x, acc.y * invl + cb.y,
                        acc.z * invl + cb.z, acc.w * invl + cb.w);
        ((float4*)(g_xg + (size_t)warp * D_))[lane] = o;
    }

    if (STATS) {
        float s = o.x + o.y + o.z + o.w;
        float q = o.x * o.x + o.y * o.y + o.z * o.z + o.w * o.w;
#pragma unroll
        for (int of = 16; of > 0; of >>= 1) {
            s += __shfl_xor_sync(0xffffffffu, s, of);
            q += __shfl_xor_sync(0xffffffffu, q, of);
        }
        if (lane == 0) { ssum[wid] = s; ssq[wid] = q; }
        __syncthreads();
        if (tid == 0) {
            double S = 0.0, Q = 0.0;
#pragma unroll
            for (int i = 0; i < 8; i++) { S += (double)ssum[i]; Q += (double)ssq[i]; }
            atomicAdd(&g_lnred[slot * 2 + 0], S);
            atomicAdd(&g_lnred[slot * 2 + 1], Q);
        }
    }
}

// -------------------- BatchNorm --------------------
__global__ void bnstats_kernel(const float* __restrict__ out) {
    int c = threadIdx.x;
    float s = 0.f, q = 0.f;
    for (int r = blockIdx.x; r < N_; r += gridDim.x) {
        float v = out[(size_t)r * D_ + c];
        s += v; q += v * v;
    }
    atomicAdd(&g_bnsum[c], s);
    atomicAdd(&g_bnsq[c], q);
}

__global__ void bnnorm_kernel(float* __restrict__ out,
                              const float* __restrict__ bng,
                              const float* __restrict__ bnb) {
    int i = blockIdx.x * blockDim.x + threadIdx.x;
    if (i >= N_ * 32) return;
    int c4 = i & 31;
    float4 v  = ((float4*)out)[i];
    float4 su = ((const float4*)g_bnsum)[c4];
    float4 qu = ((const float4*)g_bnsq)[c4];
    float4 g  = ((const float4*)bng)[c4];
    float4 b  = ((const float4*)bnb)[c4];
    const float invN = 1.f / (float)N_;
    float mu, var;
    mu = su.x * invN; var = qu.x * invN - mu * mu;
    v.x = (v.x - mu) * rsqrtf(var + EPS_) * g.x + b.x;
    mu = su.y * invN; var = qu.y * invN - mu * mu;
    v.y = (v.y - mu) * rsqrtf(var + EPS_) * g.y + b.y;
    mu = su.z * invN; var = qu.z * invN - mu * mu;
    v.z = (v.z - mu) * rsqrtf(var + EPS_) * g.z + b.z;
    mu = su.w * invN; var = qu.w * invN - mu * mu;
    v.w = (v.w - mu) * rsqrtf(var + EPS_) * g.w + b.w;
    ((float4*)out)[i] = v;
}

// -------------------- launch --------------------
extern "C" void kernel_launch(void* const* d_in, const int* in_sizes, int n_in,
                              void* d_out, int out_size) {
    const int*   x    = (const int*)d_in[0];
    const int*   ei   = (const int*)d_in[1];
    const float* emb  = (const float*)d_in[2];
    const float* Wl   = (const float*)d_in[3];
    const float* bl   = (const float*)d_in[4];
    const float* Wr   = (const float*)d_in[5];
    const float* br   = (const float*)d_in[6];
    const float* att  = (const float*)d_in[7];
    const float* cb   = (const float*)d_in[8];
    const float* lng  = (const float*)d_in[9];
    const float* lnb  = (const float*)d_in[10];
    const float* linW = (const float*)d_in[11];
    const float* linb = (const float*)d_in[12];
    const float* bng  = (const float*)d_in[13];
    const float* bnb  = (const float*)d_in[14];
    float* out = (float*)d_out;

    float *p_h, *p_xg, *p_xl, *p_xr, *p_Binv;
    uint32_t *p_B0, *p_B1;
    cudaGetSymbolAddress((void**)&p_h,  g_h);
    cudaGetSymbolAddress((void**)&p_xg, g_xg);
    cudaGetSymbolAddress((void**)&p_xl, g_xl);
    cudaGetSymbolAddress((void**)&p_xr, g_xr);
    cudaGetSymbolAddress((void**)&p_B0, g_B0);
    cudaGetSymbolAddress((void**)&p_B1, g_B1);
    cudaGetSymbolAddress((void**)&p_Binv, g_Binv);

    const int TPB = 256;
    zero_kernel<<<(N_ + TPB - 1) / TPB, TPB>>>();
    gather_kernel<<<(N_ * 32 + TPB - 1) / TPB, TPB>>>(x, emb);
    hist_kernel<<<(E2_ + TPB - 1) / TPB, TPB>>>(ei);
    scan1_kernel<<<30, 1024>>>();
    scan2_kernel<<<1, 32>>>();
    scan3_kernel<<<30, 1024>>>();
    scatter_kernel<<<(E2_ + TPB - 1) / TPB, TPB>>>(ei);
    bcolmax_kernel<<<13, 128>>>(Wl, Wr, linW);
    bpack_kernel<<<(13 * 4096 + 255) / 256, 256>>>(Wl, Wr, linW);

    const int GEMM_GRID = (N_ + 63) / 64;            // 469
    const int AGG_GRID  = (N_ * 32 + TPB - 1) / TPB; // warp per node

    for (int i = 0; i < L_; i++) {
        const float* Ain = (i == 0) ? p_h : p_xg;
        const uint32_t* B0L = p_B0 + (size_t)i * 4096;
        const uint32_t* B1L = p_B1 + (size_t)i * 4096;
        const uint32_t* B0R = p_B0 + (size_t)(6 + i) * 4096;
        const uint32_t* B1R = p_B1 + (size_t)(6 + i) * 4096;
        const float* tL = p_Binv + (size_t)i * 128;
        const float* tR = p_Binv + (size_t)(6 + i) * 128;
        if (i == 0) {
            gat_gemm<0,2><<<GEMM_GRID, 256, GSMEM>>>(
                Ain, nullptr, B0L, B1L, B0R, B1R, tL, tR,
                bl + i * D_, br + i * D_, p_xl, p_xr, nullptr, nullptr, 0);
        } else {
            gat_gemm<1,2><<<GEMM_GRID, 256, GSMEM>>>(
                Ain, nullptr, B0L, B1L, B0R, B1R, tL, tR,
                bl + i * D_, br + i * D_, p_xl, p_xr,
                lng + (i - 1) * D_, lnb + (i - 1) * D_, i - 1);
        }
        if (i < L_ - 1)
            agg_kernel<1><<<AGG_GRID, 256>>>(att + i * D_, cb + i * D_, i);
        else
            agg_kernel<0><<<AGG_GRID, 256>>>(att + i * D_, cb + i * D_, 0);
    }

    gat_gemm<2,1><<<GEMM_GRID, 256, GSMEM>>>(
        p_xg, p_h, p_B0 + (size_t)12 * 4096, p_B1 + (size_t)12 * 4096,
        nullptr, nullptr, p_Binv + (size_t)12 * 128, nullptr,
        linb, nullptr, out, nullptr, nullptr, nullptr, 0);
    bnstats_kernel<<<256, D_>>>(out);
    bnnorm_kernel<<<(N_ * 32 + TPB - 1) / TPB, TPB>>>(out, bng, bnb);
}